// round 1
// baseline (speedup 1.0000x reference)
#include <cuda_runtime.h>

#define NN 50000
#define NE 600000
#define DD 128

// ---------------- scratch (static device globals; no allocation) ----------------
__device__ float g_xw[NN * DD];     // x @ W, 25.6 MB
__device__ float g_deg[NN];
__device__ float g_dinv[NN];
__device__ float g_sum[DD];
__device__ float g_sumsq[DD];
__device__ float g_scale[DD];
__device__ float g_shift[DD];
__device__ int   g_is64;

// ---------------- dtype detection for edge_index (int32 vs int64) ----------------
// Values are in [0, 50000); if stored as int64 (little-endian), every odd 32-bit
// word is 0. If int32, odd words are random edge ids (nonzero w.p. ~1-1/50000).
__global__ void detect_kernel(const unsigned int* __restrict__ e) {
    if (threadIdx.x == 0 && blockIdx.x == 0) {
        int is64 = 1;
        #pragma unroll
        for (int i = 0; i < 16; i++) {
            if (e[2 * i + 1] != 0u) { is64 = 0; break; }
        }
        g_is64 = is64;
    }
}

// ---------------- init: z=0 (d_out as accumulator), deg=1 (self loop), stats=0 ----
__global__ void init_kernel(float* __restrict__ z) {
    int gid = blockIdx.x * blockDim.x + threadIdx.x;
    if (gid < NN * DD) z[gid] = 0.0f;
    if (gid < NN)      g_deg[gid] = 1.0f;   // self-loop contributes 1 to in-degree
    if (gid < DD)     { g_sum[gid] = 0.0f; g_sumsq[gid] = 0.0f; }
}

// ---------------- GEMM: g_xw = x @ W  (16 rows per 128-thread block) -------------
__global__ void __launch_bounds__(128) gemm_kernel(const float* __restrict__ x,
                                                   const float* __restrict__ W) {
    __shared__ float xs[16][DD];
    const int tid = threadIdx.x;
    const int r0  = blockIdx.x * 16;

    #pragma unroll
    for (int idx = tid; idx < 16 * DD; idx += 128)
        xs[idx >> 7][idx & 127] = x[(r0 + (idx >> 7)) * DD + (idx & 127)];
    __syncthreads();

    const int c  = tid & 31;   // float4 column group 0..31
    const int rq = tid >> 5;   // row quad 0..3 -> rows r0 + rq*4 .. +3
    float4 a0 = make_float4(0.f, 0.f, 0.f, 0.f), a1 = a0, a2 = a0, a3 = a0;
    const float4* __restrict__ W4 = (const float4*)W;

    #pragma unroll 8
    for (int k = 0; k < DD; k++) {
        float4 w = W4[k * 32 + c];   // L1-resident (W is 64 KB)
        float x0 = xs[rq * 4 + 0][k];
        float x1 = xs[rq * 4 + 1][k];
        float x2 = xs[rq * 4 + 2][k];
        float x3 = xs[rq * 4 + 3][k];
        a0.x += x0 * w.x; a0.y += x0 * w.y; a0.z += x0 * w.z; a0.w += x0 * w.w;
        a1.x += x1 * w.x; a1.y += x1 * w.y; a1.z += x1 * w.z; a1.w += x1 * w.w;
        a2.x += x2 * w.x; a2.y += x2 * w.y; a2.z += x2 * w.z; a2.w += x2 * w.w;
        a3.x += x3 * w.x; a3.y += x3 * w.y; a3.z += x3 * w.z; a3.w += x3 * w.w;
    }

    float4* __restrict__ out4 = (float4*)g_xw;
    const int rb = r0 + rq * 4;
    out4[(rb + 0) * 32 + c] = a0;
    out4[(rb + 1) * 32 + c] = a1;
    out4[(rb + 2) * 32 + c] = a2;
    out4[(rb + 3) * 32 + c] = a3;
}

// ---------------- degree over dst ----------------
__global__ void deg_kernel(const void* __restrict__ eidx) {
    int t = blockIdx.x * blockDim.x + threadIdx.x;
    if (t >= NE) return;
    long long d;
    if (g_is64) d = ((const long long*)eidx)[NE + t];
    else        d = ((const int*)eidx)[NE + t];
    atomicAdd(&g_deg[d], 1.0f);
}

__global__ void dinv_kernel() {
    int i = blockIdx.x * blockDim.x + threadIdx.x;
    if (i < NN) g_dinv[i] = rsqrtf(g_deg[i]);   // deg >= 1 always (self loop)
}

// ---------------- edge scatter: one warp per edge, red.add.v4.f32 ---------------
__global__ void __launch_bounds__(256) scatter_kernel(const void* __restrict__ eidx,
                                                      float* __restrict__ z) {
    int gid = blockIdx.x * blockDim.x + threadIdx.x;
    int e = gid >> 5;
    int l = gid & 31;
    if (e >= NE) return;

    long long s, d;
    if (g_is64) {
        s = ((const long long*)eidx)[e];
        d = ((const long long*)eidx)[NE + e];
    } else {
        s = ((const int*)eidx)[e];
        d = ((const int*)eidx)[NE + e];
    }
    float norm = g_dinv[s] * g_dinv[d];

    const float4* __restrict__ xw4 = (const float4*)g_xw;
    float4 v = xw4[(long long)s * 32 + l];
    float* zp = z + ((long long)d * DD + l * 4);
    asm volatile("red.global.add.v4.f32 [%0], {%1,%2,%3,%4};"
                 :: "l"(zp), "f"(v.x * norm), "f"(v.y * norm),
                    "f"(v.z * norm), "f"(v.w * norm)
                 : "memory");
}

// ------- fused: self-loop add + bias + ReLU + writeback + BN partial stats -------
__global__ void __launch_bounds__(128) stats_kernel(float* __restrict__ z,
                                                    const float* __restrict__ bias) {
    const int j = threadIdx.x;   // column
    const float b = bias[j];
    float lsum = 0.f, lsq = 0.f;
    for (int row = blockIdx.x; row < NN; row += gridDim.x) {
        float di = g_dinv[row];
        float v  = z[row * DD + j] + g_xw[row * DD + j] * (di * di) + b;
        v = fmaxf(v, 0.0f);
        z[row * DD + j] = v;
        lsum += v;
        lsq  += v * v;
    }
    atomicAdd(&g_sum[j], lsum);
    atomicAdd(&g_sumsq[j], lsq);
}

// ---------------- BN affine params ----------------
__global__ void params_kernel(const float* __restrict__ gamma,
                              const float* __restrict__ beta) {
    int j = threadIdx.x;
    float mean = g_sum[j] * (1.0f / NN);
    float var  = g_sumsq[j] * (1.0f / NN) - mean * mean;
    float sc   = gamma[j] * rsqrtf(var + 1e-5f);
    g_scale[j] = sc;
    g_shift[j] = beta[j] - mean * sc;
}

// ---------------- fused normalize + dropout (float4) ----------------
__global__ void __launch_bounds__(256) final_kernel(const float* __restrict__ u,
                                                    float* __restrict__ z) {
    int gid = blockIdx.x * blockDim.x + threadIdx.x;
    if (gid >= NN * 32) return;
    int j4 = (gid & 31) * 4;

    float4 v  = ((const float4*)z)[gid];
    float4 uu = ((const float4*)u)[gid];
    float s0 = g_scale[j4 + 0], s1 = g_scale[j4 + 1], s2 = g_scale[j4 + 2], s3 = g_scale[j4 + 3];
    float h0 = g_shift[j4 + 0], h1 = g_shift[j4 + 1], h2 = g_shift[j4 + 2], h3 = g_shift[j4 + 3];
    const float inv_keep = 1.0f / 0.9f;

    float4 r;
    r.x = (uu.x > 0.1f) ? (v.x * s0 + h0) * inv_keep : 0.0f;
    r.y = (uu.y > 0.1f) ? (v.y * s1 + h1) * inv_keep : 0.0f;
    r.z = (uu.z > 0.1f) ? (v.z * s2 + h2) * inv_keep : 0.0f;
    r.w = (uu.w > 0.1f) ? (v.w * s3 + h3) * inv_keep : 0.0f;
    ((float4*)z)[gid] = r;
}

// ---------------- launch ----------------
extern "C" void kernel_launch(void* const* d_in, const int* in_sizes, int n_in,
                              void* d_out, int out_size) {
    const float* x      = (const float*)d_in[0];
    const float* weight = (const float*)d_in[1];
    const float* bias   = (const float*)d_in[2];
    const float* gamma  = (const float*)d_in[3];
    const float* beta   = (const float*)d_in[4];
    const float* drop_u = (const float*)d_in[5];
    const void*  eidx   = d_in[6];

    float* z = (float*)d_out;   // used as the segment-sum accumulator in place

    detect_kernel<<<1, 32>>>((const unsigned int*)eidx);
    init_kernel<<<(NN * DD + 255) / 256, 256>>>(z);
    gemm_kernel<<<NN / 16, 128>>>(x, weight);
    deg_kernel<<<(NE + 255) / 256, 256>>>(eidx);
    dinv_kernel<<<(NN + 255) / 256, 256>>>();
    scatter_kernel<<<(NE * 32 + 255) / 256, 256>>>(eidx, z);
    stats_kernel<<<256, 128>>>(z, bias);
    params_kernel<<<1, DD>>>(gamma, beta);
    final_kernel<<<(NN * 32 + 255) / 256, 256>>>(drop_u, z);
}

// round 2
// speedup vs baseline: 1.4048x; 1.4048x over previous
#include <cuda_runtime.h>

#define NN 50000
#define NE 600000
#define DD 128

// ---------------- scratch (static device globals; no allocation) ----------------
__device__ float g_xw[NN * DD];                 // x @ W, 25.6 MB
__device__ int   g_degi[NN];                    // real in-degree (no self loop)
__device__ int   g_start[NN];                   // CSR start offsets
__device__ int   g_cur[NN];                     // fill cursors (== end after fill)
__device__ unsigned long long g_adj[NE];        // packed {norm(f32)<<32 | src}
__device__ float g_dinv[NN];
__device__ float g_sum[DD];
__device__ float g_sumsq[DD];
__device__ float g_scale[DD];
__device__ float g_shift[DD];
__device__ int   g_is64;

// ---------------- dtype detection for edge_index (int32 vs int64) ----------------
__global__ void detect_kernel(const unsigned int* __restrict__ e) {
    if (threadIdx.x == 0 && blockIdx.x == 0) {
        int is64 = 1;
        #pragma unroll
        for (int i = 0; i < 16; i++) {
            if (e[2 * i + 1] != 0u) { is64 = 0; break; }
        }
        g_is64 = is64;
    }
}

// ---------------- init: deg=0, stats=0 (no z zeroing needed anymore) -------------
__global__ void init_kernel() {
    int gid = blockIdx.x * blockDim.x + threadIdx.x;
    if (gid < NN) g_degi[gid] = 0;
    if (gid < DD) { g_sum[gid] = 0.0f; g_sumsq[gid] = 0.0f; }
}

// ---------------- degree over dst (real edges only) ----------------
__global__ void deg_kernel(const void* __restrict__ eidx) {
    int t = blockIdx.x * blockDim.x + threadIdx.x;
    if (t >= NE) return;
    int d;
    if (g_is64) d = (int)((const long long*)eidx)[NE + t];
    else        d = ((const int*)eidx)[NE + t];
    atomicAdd(&g_degi[d], 1);
}

// ---------------- single-block prefix scan: offsets + cursors + dinv -------------
__global__ void __launch_bounds__(1024) scan_kernel() {
    __shared__ int wsums[32];
    const int tid = threadIdx.x, lane = tid & 31, wid = tid >> 5;
    int carry = 0;
    for (int base = 0; base < NN; base += 1024) {
        int i = base + tid;
        int d = (i < NN) ? g_degi[i] : 0;
        int v = d;
        #pragma unroll
        for (int o = 1; o < 32; o <<= 1) {
            int t = __shfl_up_sync(0xffffffffu, v, o);
            if (lane >= o) v += t;
        }
        if (lane == 31) wsums[wid] = v;
        __syncthreads();
        if (wid == 0) {
            int wv = wsums[lane];
            #pragma unroll
            for (int o = 1; o < 32; o <<= 1) {
                int t = __shfl_up_sync(0xffffffffu, wv, o);
                if (lane >= o) wv += t;
            }
            wsums[lane] = wv;
        }
        __syncthreads();
        int excl = carry + (wid > 0 ? wsums[wid - 1] : 0) + (v - d);
        if (i < NN) {
            g_start[i] = excl;
            g_cur[i]   = excl;
            g_dinv[i]  = rsqrtf((float)d + 1.0f);   // +1 = self loop
        }
        int total = wsums[31];
        __syncthreads();
        carry += total;
    }
}

// ---------------- adjacency fill: packed {norm, src} per edge --------------------
__global__ void fill_kernel(const void* __restrict__ eidx) {
    int t = blockIdx.x * blockDim.x + threadIdx.x;
    if (t >= NE) return;
    int s, d;
    if (g_is64) {
        s = (int)((const long long*)eidx)[t];
        d = (int)((const long long*)eidx)[NE + t];
    } else {
        s = ((const int*)eidx)[t];
        d = ((const int*)eidx)[NE + t];
    }
    float norm = g_dinv[s] * g_dinv[d];
    int p = atomicAdd(&g_cur[d], 1);
    g_adj[p] = ((unsigned long long)__float_as_uint(norm) << 32) | (unsigned int)s;
}

// ---------------- GEMM: g_xw = x @ W, packed fma.rn.f32x2 ------------------------
// 32 rows per 128-thread block. Thread = 8 rows x 4 cols. x duplicated {x,x} in smem.
__global__ void __launch_bounds__(128) gemm_kernel(const float* __restrict__ x,
                                                   const float* __restrict__ W) {
    __shared__ unsigned long long xs[32][DD];   // 32 KB
    const int tid = threadIdx.x;
    const int r0  = blockIdx.x * 32;

    for (int idx = tid; idx < 32 * DD; idx += 128) {
        int row = idx >> 7, k = idx & 127;
        float v = (r0 + row < NN) ? x[(size_t)(r0 + row) * DD + k] : 0.0f;
        unsigned int u = __float_as_uint(v);
        xs[row][k] = ((unsigned long long)u << 32) | u;
    }
    __syncthreads();

    const int cg = tid & 31;    // column group of 4 (float4)
    const int rg = tid >> 5;    // row group of 8
    unsigned long long a[8][2];
    #pragma unroll
    for (int r = 0; r < 8; r++) { a[r][0] = 0ull; a[r][1] = 0ull; }

    const float4* __restrict__ W4 = (const float4*)W;
    #pragma unroll 4
    for (int k = 0; k < DD; k++) {
        float4 w = W4[k * 32 + cg];             // L1-resident (64 KB)
        unsigned long long wxy, wzw;
        asm("mov.b64 %0, {%1,%2};" : "=l"(wxy) : "f"(w.x), "f"(w.y));
        asm("mov.b64 %0, {%1,%2};" : "=l"(wzw) : "f"(w.z), "f"(w.w));
        #pragma unroll
        for (int r = 0; r < 8; r++) {
            unsigned long long xd = xs[rg * 8 + r][k];
            asm("fma.rn.f32x2 %0, %1, %2, %0;" : "+l"(a[r][0]) : "l"(xd), "l"(wxy));
            asm("fma.rn.f32x2 %0, %1, %2, %0;" : "+l"(a[r][1]) : "l"(xd), "l"(wzw));
        }
    }

    float4* __restrict__ out4 = (float4*)g_xw;
    #pragma unroll
    for (int r = 0; r < 8; r++) {
        int row = r0 + rg * 8 + r;
        if (row < NN) {
            float4 o;
            asm("mov.b64 {%0,%1}, %2;" : "=f"(o.x), "=f"(o.y) : "l"(a[r][0]));
            asm("mov.b64 {%0,%1}, %2;" : "=f"(o.z), "=f"(o.w) : "l"(a[r][1]));
            out4[(size_t)row * 32 + cg] = o;
        }
    }
}

// ---- gather: warp per node; self-loop + neighbors + bias + ReLU + BN stats ------
__global__ void __launch_bounds__(256) gather_kernel(const float* __restrict__ bias,
                                                     float* __restrict__ z) {
    const int tid   = threadIdx.x;
    const int lane  = tid & 31;
    const int wid   = tid >> 5;
    const int warpg = (blockIdx.x * 256 + tid) >> 5;
    const int nwarp = gridDim.x * 8;

    const float4* __restrict__ xw4   = (const float4*)g_xw;
    const float4* __restrict__ bias4 = (const float4*)bias;
    float4*       __restrict__ z4    = (float4*)z;

    const float4 b = bias4[lane];
    float4 ls = make_float4(0.f, 0.f, 0.f, 0.f);
    float4 lq = ls;

    for (int node = warpg; node < NN; node += nwarp) {
        int beg = g_start[node];
        int end = g_cur[node];
        float di = g_dinv[node];
        float4 acc = __ldcg(&xw4[(size_t)node * 32 + lane]);
        float sn = di * di;
        acc.x *= sn; acc.y *= sn; acc.z *= sn; acc.w *= sn;

        int i = beg;
        for (; i + 4 <= end; i += 4) {
            unsigned long long e0 = g_adj[i];
            unsigned long long e1 = g_adj[i + 1];
            unsigned long long e2 = g_adj[i + 2];
            unsigned long long e3 = g_adj[i + 3];
            float4 v0 = __ldcg(&xw4[(size_t)(unsigned)(e0 & 0xffffffffu) * 32 + lane]);
            float4 v1 = __ldcg(&xw4[(size_t)(unsigned)(e1 & 0xffffffffu) * 32 + lane]);
            float4 v2 = __ldcg(&xw4[(size_t)(unsigned)(e2 & 0xffffffffu) * 32 + lane]);
            float4 v3 = __ldcg(&xw4[(size_t)(unsigned)(e3 & 0xffffffffu) * 32 + lane]);
            float n0 = __uint_as_float((unsigned)(e0 >> 32));
            float n1 = __uint_as_float((unsigned)(e1 >> 32));
            float n2 = __uint_as_float((unsigned)(e2 >> 32));
            float n3 = __uint_as_float((unsigned)(e3 >> 32));
            acc.x += v0.x * n0; acc.y += v0.y * n0; acc.z += v0.z * n0; acc.w += v0.w * n0;
            acc.x += v1.x * n1; acc.y += v1.y * n1; acc.z += v1.z * n1; acc.w += v1.w * n1;
            acc.x += v2.x * n2; acc.y += v2.y * n2; acc.z += v2.z * n2; acc.w += v2.w * n2;
            acc.x += v3.x * n3; acc.y += v3.y * n3; acc.z += v3.z * n3; acc.w += v3.w * n3;
        }
        for (; i < end; i++) {
            unsigned long long e0 = g_adj[i];
            float4 v0 = __ldcg(&xw4[(size_t)(unsigned)(e0 & 0xffffffffu) * 32 + lane]);
            float n0 = __uint_as_float((unsigned)(e0 >> 32));
            acc.x += v0.x * n0; acc.y += v0.y * n0; acc.z += v0.z * n0; acc.w += v0.w * n0;
        }

        float4 v;
        v.x = fmaxf(acc.x + b.x, 0.0f);
        v.y = fmaxf(acc.y + b.y, 0.0f);
        v.z = fmaxf(acc.z + b.z, 0.0f);
        v.w = fmaxf(acc.w + b.w, 0.0f);
        z4[(size_t)node * 32 + lane] = v;

        ls.x += v.x; ls.y += v.y; ls.z += v.z; ls.w += v.w;
        lq.x += v.x * v.x; lq.y += v.y * v.y; lq.z += v.z * v.z; lq.w += v.w * v.w;
    }

    // block reduction of per-thread BN partials (lane owns cols 4*lane..4*lane+3)
    __shared__ float rs[8][DD];
    __shared__ float rq[8][DD];
    ((float4*)&rs[wid][0])[lane] = ls;
    ((float4*)&rq[wid][0])[lane] = lq;
    __syncthreads();
    if (tid < DD) {
        float a = 0.f, q = 0.f;
        #pragma unroll
        for (int w = 0; w < 8; w++) { a += rs[w][tid]; q += rq[w][tid]; }
        atomicAdd(&g_sum[tid], a);
        atomicAdd(&g_sumsq[tid], q);
    }
}

// ---------------- BN affine params ----------------
__global__ void params_kernel(const float* __restrict__ gamma,
                              const float* __restrict__ beta) {
    int j = threadIdx.x;
    float mean = g_sum[j] * (1.0f / NN);
    float var  = g_sumsq[j] * (1.0f / NN) - mean * mean;
    float sc   = gamma[j] * rsqrtf(var + 1e-5f);
    g_scale[j] = sc;
    g_shift[j] = beta[j] - mean * sc;
}

// ---------------- fused normalize + dropout (float4) ----------------
__global__ void __launch_bounds__(256) final_kernel(const float* __restrict__ u,
                                                    float* __restrict__ z) {
    int gid = blockIdx.x * blockDim.x + threadIdx.x;
    if (gid >= NN * 32) return;
    int j4 = (gid & 31) * 4;

    float4 v  = ((const float4*)z)[gid];
    float4 uu = ((const float4*)u)[gid];
    float s0 = g_scale[j4 + 0], s1 = g_scale[j4 + 1], s2 = g_scale[j4 + 2], s3 = g_scale[j4 + 3];
    float h0 = g_shift[j4 + 0], h1 = g_shift[j4 + 1], h2 = g_shift[j4 + 2], h3 = g_shift[j4 + 3];
    const float inv_keep = 1.0f / 0.9f;

    float4 r;
    r.x = (uu.x > 0.1f) ? (v.x * s0 + h0) * inv_keep : 0.0f;
    r.y = (uu.y > 0.1f) ? (v.y * s1 + h1) * inv_keep : 0.0f;
    r.z = (uu.z > 0.1f) ? (v.z * s2 + h2) * inv_keep : 0.0f;
    r.w = (uu.w > 0.1f) ? (v.w * s3 + h3) * inv_keep : 0.0f;
    ((float4*)z)[gid] = r;
}

// ---------------- launch ----------------
extern "C" void kernel_launch(void* const* d_in, const int* in_sizes, int n_in,
                              void* d_out, int out_size) {
    const float* x      = (const float*)d_in[0];
    const float* weight = (const float*)d_in[1];
    const float* bias   = (const float*)d_in[2];
    const float* gamma  = (const float*)d_in[3];
    const float* beta   = (const float*)d_in[4];
    const float* drop_u = (const float*)d_in[5];
    const void*  eidx   = d_in[6];

    float* z = (float*)d_out;

    detect_kernel<<<1, 32>>>((const unsigned int*)eidx);
    init_kernel<<<(NN + 255) / 256, 256>>>();
    deg_kernel<<<(NE + 255) / 256, 256>>>(eidx);
    scan_kernel<<<1, 1024>>>();
    fill_kernel<<<(NE + 255) / 256, 256>>>(eidx);
    gemm_kernel<<<(NN + 31) / 32, 128>>>(x, weight);
    gather_kernel<<<592, 256>>>(bias, z);
    params_kernel<<<1, DD>>>(gamma, beta);
    final_kernel<<<(NN * 32 + 255) / 256, 256>>>(drop_u, z);
}

// round 3
// speedup vs baseline: 1.7174x; 1.2225x over previous
#include <cuda_runtime.h>

#define NN 50000
#define NE 600000
#define DD 128
#define SCAN_B 1024
#define SCAN_G ((NN + SCAN_B - 1) / SCAN_B)   // 49

// ---------------- scratch (static device globals; no allocation) ----------------
__device__ float g_xw[NN * DD];                 // x @ W, 25.6 MB
__device__ int   g_degi[NN];                    // real in-degree (no self loop)
__device__ int   g_start[NN];                   // CSR start offsets
__device__ int   g_cur[NN];                     // fill cursors (== end after fill)
__device__ unsigned long long g_adj[NE];        // packed {norm(f32)<<32 | src}
__device__ float g_dinv[NN];
__device__ int   g_bsum[SCAN_G];                // per-block degree totals
__device__ int   g_boff[SCAN_G];                // exclusive scan of totals
__device__ float g_sum[DD];
__device__ float g_sumsq[DD];
__device__ float g_scale[DD];
__device__ float g_shift[DD];
__device__ int   g_is64;

// ---------------- dtype detection for edge_index (int32 vs int64) ----------------
__global__ void detect_kernel(const unsigned int* __restrict__ e) {
    if (threadIdx.x == 0 && blockIdx.x == 0) {
        int is64 = 1;
        #pragma unroll
        for (int i = 0; i < 16; i++) {
            if (e[2 * i + 1] != 0u) { is64 = 0; break; }
        }
        g_is64 = is64;
    }
}

// ---------------- init: deg=0, stats=0 ----------------
__global__ void init_kernel() {
    int gid = blockIdx.x * blockDim.x + threadIdx.x;
    if (gid < NN) g_degi[gid] = 0;
    if (gid < DD) { g_sum[gid] = 0.0f; g_sumsq[gid] = 0.0f; }
}

// ---------------- degree over dst (real edges only) ----------------
__global__ void deg_kernel(const void* __restrict__ eidx) {
    int t = blockIdx.x * blockDim.x + threadIdx.x;
    if (t >= NE) return;
    int d;
    if (g_is64) d = (int)((const long long*)eidx)[NE + t];
    else        d = ((const int*)eidx)[NE + t];
    atomicAdd(&g_degi[d], 1);
}

// ---------------- scan phase 1: per-block totals + dinv ----------------
__global__ void __launch_bounds__(SCAN_B) scan1_kernel() {
    __shared__ int wsums[32];
    const int tid = threadIdx.x, lane = tid & 31, wid = tid >> 5;
    const int i = blockIdx.x * SCAN_B + tid;
    int d = (i < NN) ? g_degi[i] : 0;
    if (i < NN) g_dinv[i] = rsqrtf((float)d + 1.0f);   // +1 = self loop

    int v = d;
    #pragma unroll
    for (int o = 16; o > 0; o >>= 1) v += __shfl_down_sync(0xffffffffu, v, o);
    if (lane == 0) wsums[wid] = v;
    __syncthreads();
    if (wid == 0) {
        int wv = wsums[lane];
        #pragma unroll
        for (int o = 16; o > 0; o >>= 1) wv += __shfl_down_sync(0xffffffffu, wv, o);
        if (lane == 0) g_bsum[blockIdx.x] = wv;
    }
}

// ---------------- scan phase 2: exclusive scan of 49 block totals ----------------
__global__ void scan2_kernel() {
    const int lane = threadIdx.x;                 // 64 threads
    int v = (lane < SCAN_G) ? g_bsum[lane] : 0;
    int acc = v;
    #pragma unroll
    for (int o = 1; o < 64; o <<= 1) {
        int t = __shfl_up_sync(0xffffffffu, acc, o, 32);
        if ((lane & 31) >= o) acc += t;
    }
    __shared__ int w0;
    if (lane == 31) w0 = acc;
    __syncthreads();
    int excl = acc - v + ((lane >= 32) ? w0 : 0);
    if (lane < SCAN_G) g_boff[lane] = excl;
}

// ---------------- scan phase 3: block-local scan + offset -> start/cur -----------
__global__ void __launch_bounds__(SCAN_B) scan3_kernel() {
    __shared__ int wsums[32];
    const int tid = threadIdx.x, lane = tid & 31, wid = tid >> 5;
    const int i = blockIdx.x * SCAN_B + tid;
    int d = (i < NN) ? g_degi[i] : 0;
    int v = d;
    #pragma unroll
    for (int o = 1; o < 32; o <<= 1) {
        int t = __shfl_up_sync(0xffffffffu, v, o);
        if (lane >= o) v += t;
    }
    if (lane == 31) wsums[wid] = v;
    __syncthreads();
    if (wid == 0) {
        int wv = wsums[lane];
        #pragma unroll
        for (int o = 1; o < 32; o <<= 1) {
            int t = __shfl_up_sync(0xffffffffu, wv, o);
            if (lane >= o) wv += t;
        }
        wsums[lane] = wv;
    }
    __syncthreads();
    if (i < NN) {
        int excl = g_boff[blockIdx.x] + (wid > 0 ? wsums[wid - 1] : 0) + (v - d);
        g_start[i] = excl;
        g_cur[i]   = excl;
    }
}

// ---------------- adjacency fill: packed {norm, src} per edge --------------------
__global__ void fill_kernel(const void* __restrict__ eidx) {
    int t = blockIdx.x * blockDim.x + threadIdx.x;
    if (t >= NE) return;
    int s, d;
    if (g_is64) {
        s = (int)((const long long*)eidx)[t];
        d = (int)((const long long*)eidx)[NE + t];
    } else {
        s = ((const int*)eidx)[t];
        d = ((const int*)eidx)[NE + t];
    }
    float norm = g_dinv[s] * g_dinv[d];
    int p = atomicAdd(&g_cur[d], 1);
    g_adj[p] = ((unsigned long long)__float_as_uint(norm) << 32) | (unsigned int)s;
}

// ---------------- GEMM: g_xw = x @ W, packed fma.rn.f32x2 ------------------------
__global__ void __launch_bounds__(128) gemm_kernel(const float* __restrict__ x,
                                                   const float* __restrict__ W) {
    __shared__ unsigned long long xs[32][DD];   // 32 KB
    const int tid = threadIdx.x;
    const int r0  = blockIdx.x * 32;

    for (int idx = tid; idx < 32 * DD; idx += 128) {
        int row = idx >> 7, k = idx & 127;
        float v = (r0 + row < NN) ? x[(size_t)(r0 + row) * DD + k] : 0.0f;
        unsigned int u = __float_as_uint(v);
        xs[row][k] = ((unsigned long long)u << 32) | u;
    }
    __syncthreads();

    const int cg = tid & 31;    // column group of 4 (float4)
    const int rg = tid >> 5;    // row group of 8
    unsigned long long a[8][2];
    #pragma unroll
    for (int r = 0; r < 8; r++) { a[r][0] = 0ull; a[r][1] = 0ull; }

    const float4* __restrict__ W4 = (const float4*)W;
    #pragma unroll 4
    for (int k = 0; k < DD; k++) {
        float4 w = W4[k * 32 + cg];             // L1-resident (64 KB)
        unsigned long long wxy, wzw;
        asm("mov.b64 %0, {%1,%2};" : "=l"(wxy) : "f"(w.x), "f"(w.y));
        asm("mov.b64 %0, {%1,%2};" : "=l"(wzw) : "f"(w.z), "f"(w.w));
        #pragma unroll
        for (int r = 0; r < 8; r++) {
            unsigned long long xd = xs[rg * 8 + r][k];
            asm("fma.rn.f32x2 %0, %1, %2, %0;" : "+l"(a[r][0]) : "l"(xd), "l"(wxy));
            asm("fma.rn.f32x2 %0, %1, %2, %0;" : "+l"(a[r][1]) : "l"(xd), "l"(wzw));
        }
    }

    float4* __restrict__ out4 = (float4*)g_xw;
    #pragma unroll
    for (int r = 0; r < 8; r++) {
        int row = r0 + rg * 8 + r;
        if (row < NN) {
            float4 o;
            asm("mov.b64 {%0,%1}, %2;" : "=f"(o.x), "=f"(o.y) : "l"(a[r][0]));
            asm("mov.b64 {%0,%1}, %2;" : "=f"(o.z), "=f"(o.w) : "l"(a[r][1]));
            out4[(size_t)row * 32 + cg] = o;
        }
    }
}

// ---- gather: warp per node; self-loop + neighbors + bias + ReLU + BN stats ------
__global__ void __launch_bounds__(256) gather_kernel(const float* __restrict__ bias,
                                                     float* __restrict__ z) {
    const int tid   = threadIdx.x;
    const int lane  = tid & 31;
    const int wid   = tid >> 5;
    const int warpg = (blockIdx.x * 256 + tid) >> 5;
    const int nwarp = gridDim.x * 8;

    const float4* __restrict__ xw4   = (const float4*)g_xw;
    const float4* __restrict__ bias4 = (const float4*)bias;
    float4*       __restrict__ z4    = (float4*)z;

    const float4 b = bias4[lane];
    float4 ls = make_float4(0.f, 0.f, 0.f, 0.f);
    float4 lq = ls;

    for (int node = warpg; node < NN; node += nwarp) {
        int beg = g_start[node];
        int end = g_cur[node];
        float di = g_dinv[node];
        float4 acc = __ldcg(&xw4[(size_t)node * 32 + lane]);
        float sn = di * di;
        acc.x *= sn; acc.y *= sn; acc.z *= sn; acc.w *= sn;

        int i = beg;
        for (; i + 4 <= end; i += 4) {
            unsigned long long e0 = g_adj[i];
            unsigned long long e1 = g_adj[i + 1];
            unsigned long long e2 = g_adj[i + 2];
            unsigned long long e3 = g_adj[i + 3];
            float4 v0 = __ldcg(&xw4[(size_t)(unsigned)(e0 & 0xffffffffu) * 32 + lane]);
            float4 v1 = __ldcg(&xw4[(size_t)(unsigned)(e1 & 0xffffffffu) * 32 + lane]);
            float4 v2 = __ldcg(&xw4[(size_t)(unsigned)(e2 & 0xffffffffu) * 32 + lane]);
            float4 v3 = __ldcg(&xw4[(size_t)(unsigned)(e3 & 0xffffffffu) * 32 + lane]);
            float n0 = __uint_as_float((unsigned)(e0 >> 32));
            float n1 = __uint_as_float((unsigned)(e1 >> 32));
            float n2 = __uint_as_float((unsigned)(e2 >> 32));
            float n3 = __uint_as_float((unsigned)(e3 >> 32));
            acc.x += v0.x * n0; acc.y += v0.y * n0; acc.z += v0.z * n0; acc.w += v0.w * n0;
            acc.x += v1.x * n1; acc.y += v1.y * n1; acc.z += v1.z * n1; acc.w += v1.w * n1;
            acc.x += v2.x * n2; acc.y += v2.y * n2; acc.z += v2.z * n2; acc.w += v2.w * n2;
            acc.x += v3.x * n3; acc.y += v3.y * n3; acc.z += v3.z * n3; acc.w += v3.w * n3;
        }
        for (; i < end; i++) {
            unsigned long long e0 = g_adj[i];
            float4 v0 = __ldcg(&xw4[(size_t)(unsigned)(e0 & 0xffffffffu) * 32 + lane]);
            float n0 = __uint_as_float((unsigned)(e0 >> 32));
            acc.x += v0.x * n0; acc.y += v0.y * n0; acc.z += v0.z * n0; acc.w += v0.w * n0;
        }

        float4 v;
        v.x = fmaxf(acc.x + b.x, 0.0f);
        v.y = fmaxf(acc.y + b.y, 0.0f);
        v.z = fmaxf(acc.z + b.z, 0.0f);
        v.w = fmaxf(acc.w + b.w, 0.0f);
        z4[(size_t)node * 32 + lane] = v;

        ls.x += v.x; ls.y += v.y; ls.z += v.z; ls.w += v.w;
        lq.x += v.x * v.x; lq.y += v.y * v.y; lq.z += v.z * v.z; lq.w += v.w * v.w;
    }

    __shared__ float rs[8][DD];
    __shared__ float rq[8][DD];
    ((float4*)&rs[wid][0])[lane] = ls;
    ((float4*)&rq[wid][0])[lane] = lq;
    __syncthreads();
    if (tid < DD) {
        float a = 0.f, q = 0.f;
        #pragma unroll
        for (int w = 0; w < 8; w++) { a += rs[w][tid]; q += rq[w][tid]; }
        atomicAdd(&g_sum[tid], a);
        atomicAdd(&g_sumsq[tid], q);
    }
}

// ---------------- BN affine params ----------------
__global__ void params_kernel(const float* __restrict__ gamma,
                              const float* __restrict__ beta) {
    int j = threadIdx.x;
    float mean = g_sum[j] * (1.0f / NN);
    float var  = g_sumsq[j] * (1.0f / NN) - mean * mean;
    float sc   = gamma[j] * rsqrtf(var + 1e-5f);
    g_scale[j] = sc;
    g_shift[j] = beta[j] - mean * sc;
}

// ---------------- fused normalize + dropout (float4) ----------------
__global__ void __launch_bounds__(256) final_kernel(const float* __restrict__ u,
                                                    float* __restrict__ z) {
    int gid = blockIdx.x * blockDim.x + threadIdx.x;
    if (gid >= NN * 32) return;
    int j4 = (gid & 31) * 4;

    float4 v  = ((const float4*)z)[gid];
    float4 uu = ((const float4*)u)[gid];
    float s0 = g_scale[j4 + 0], s1 = g_scale[j4 + 1], s2 = g_scale[j4 + 2], s3 = g_scale[j4 + 3];
    float h0 = g_shift[j4 + 0], h1 = g_shift[j4 + 1], h2 = g_shift[j4 + 2], h3 = g_shift[j4 + 3];
    const float inv_keep = 1.0f / 0.9f;

    float4 r;
    r.x = (uu.x > 0.1f) ? (v.x * s0 + h0) * inv_keep : 0.0f;
    r.y = (uu.y > 0.1f) ? (v.y * s1 + h1) * inv_keep : 0.0f;
    r.z = (uu.z > 0.1f) ? (v.z * s2 + h2) * inv_keep : 0.0f;
    r.w = (uu.w > 0.1f) ? (v.w * s3 + h3) * inv_keep : 0.0f;
    ((float4*)z)[gid] = r;
}

// ---------------- launch ----------------
extern "C" void kernel_launch(void* const* d_in, const int* in_sizes, int n_in,
                              void* d_out, int out_size) {
    const float* x      = (const float*)d_in[0];
    const float* weight = (const float*)d_in[1];
    const float* bias   = (const float*)d_in[2];
    const float* gamma  = (const float*)d_in[3];
    const float* beta   = (const float*)d_in[4];
    const float* drop_u = (const float*)d_in[5];
    const void*  eidx   = d_in[6];

    float* z = (float*)d_out;

    detect_kernel<<<1, 32>>>((const unsigned int*)eidx);
    init_kernel<<<(NN + 255) / 256, 256>>>();
    deg_kernel<<<(NE + 255) / 256, 256>>>(eidx);
    scan1_kernel<<<SCAN_G, SCAN_B>>>();
    scan2_kernel<<<1, 64>>>();
    scan3_kernel<<<SCAN_G, SCAN_B>>>();
    fill_kernel<<<(NE + 255) / 256, 256>>>(eidx);
    gemm_kernel<<<(NN + 31) / 32, 128>>>(x, weight);
    gather_kernel<<<592, 256>>>(bias, z);
    params_kernel<<<1, DD>>>(gamma, beta);
    final_kernel<<<(NN * 32 + 255) / 256, 256>>>(drop_u, z);
}

// round 4
// speedup vs baseline: 1.7692x; 1.0302x over previous
#include <cuda_runtime.h>
#include <cuda_fp16.h>

#define NN 50000
#define NE 600000
#define DD 128
#define SCAN_B 1024
#define SCAN_G ((NN + SCAN_B - 1) / SCAN_B)   // 49

// ---------------- scratch (static device globals; no allocation) ----------------
__device__ __half g_xwh[NN * DD];               // x @ W in fp16, 12.8 MB
__device__ int   g_degi[NN];                    // real in-degree (no self loop)
__device__ int   g_start[NN];                   // CSR start offsets
__device__ int   g_cur[NN];                     // fill cursors (== end after fill)
__device__ unsigned long long g_adj[NE];        // packed {norm(f32)<<32 | src}
__device__ float g_dinv[NN];
__device__ int   g_bsum[SCAN_G];                // per-block degree totals
__device__ int   g_boff[SCAN_G];                // exclusive scan of totals
__device__ float g_sum[DD];
__device__ float g_sumsq[DD];
__device__ float g_scale[DD];
__device__ float g_shift[DD];
__device__ int   g_is64;

// ---------- init (deg=0, stats=0) + dtype detection for edge_index ----------
__global__ void init_kernel(const unsigned int* __restrict__ e) {
    int gid = blockIdx.x * blockDim.x + threadIdx.x;
    if (gid < NN) g_degi[gid] = 0;
    if (gid < DD) { g_sum[gid] = 0.0f; g_sumsq[gid] = 0.0f; }
    if (gid == 0) {
        // values < 50000: if int64 (LE), every odd 32-bit word is 0
        int is64 = 1;
        #pragma unroll
        for (int i = 0; i < 16; i++) {
            if (e[2 * i + 1] != 0u) { is64 = 0; break; }
        }
        g_is64 = is64;
    }
}

// ---------------- degree over dst (real edges only) ----------------
__global__ void deg_kernel(const void* __restrict__ eidx) {
    int t = blockIdx.x * blockDim.x + threadIdx.x;
    if (t >= NE) return;
    int d;
    if (g_is64) d = (int)((const long long*)eidx)[NE + t];
    else        d = ((const int*)eidx)[NE + t];
    atomicAdd(&g_degi[d], 1);
}

// ---------------- scan phase 1: per-block totals + dinv ----------------
__global__ void __launch_bounds__(SCAN_B) scan1_kernel() {
    __shared__ int wsums[32];
    const int tid = threadIdx.x, lane = tid & 31, wid = tid >> 5;
    const int i = blockIdx.x * SCAN_B + tid;
    int d = (i < NN) ? g_degi[i] : 0;
    if (i < NN) g_dinv[i] = rsqrtf((float)d + 1.0f);   // +1 = self loop

    int v = d;
    #pragma unroll
    for (int o = 16; o > 0; o >>= 1) v += __shfl_down_sync(0xffffffffu, v, o);
    if (lane == 0) wsums[wid] = v;
    __syncthreads();
    if (wid == 0) {
        int wv = wsums[lane];
        #pragma unroll
        for (int o = 16; o > 0; o >>= 1) wv += __shfl_down_sync(0xffffffffu, wv, o);
        if (lane == 0) g_bsum[blockIdx.x] = wv;
    }
}

// ---------------- scan phase 2: exclusive scan of 49 block totals ----------------
__global__ void scan2_kernel() {
    const int lane = threadIdx.x;                 // 64 threads
    int v = (lane < SCAN_G) ? g_bsum[lane] : 0;
    int acc = v;
    #pragma unroll
    for (int o = 1; o < 64; o <<= 1) {
        int t = __shfl_up_sync(0xffffffffu, acc, o, 32);
        if ((lane & 31) >= o) acc += t;
    }
    __shared__ int w0;
    if (lane == 31) w0 = acc;
    __syncthreads();
    int excl = acc - v + ((lane >= 32) ? w0 : 0);
    if (lane < SCAN_G) g_boff[lane] = excl;
}

// ---------------- scan phase 3: block-local scan + offset -> start/cur -----------
__global__ void __launch_bounds__(SCAN_B) scan3_kernel() {
    __shared__ int wsums[32];
    const int tid = threadIdx.x, lane = tid & 31, wid = tid >> 5;
    const int i = blockIdx.x * SCAN_B + tid;
    int d = (i < NN) ? g_degi[i] : 0;
    int v = d;
    #pragma unroll
    for (int o = 1; o < 32; o <<= 1) {
        int t = __shfl_up_sync(0xffffffffu, v, o);
        if (lane >= o) v += t;
    }
    if (lane == 31) wsums[wid] = v;
    __syncthreads();
    if (wid == 0) {
        int wv = wsums[lane];
        #pragma unroll
        for (int o = 1; o < 32; o <<= 1) {
            int t = __shfl_up_sync(0xffffffffu, wv, o);
            if (lane >= o) wv += t;
        }
        wsums[lane] = wv;
    }
    __syncthreads();
    if (i < NN) {
        int excl = g_boff[blockIdx.x] + (wid > 0 ? wsums[wid - 1] : 0) + (v - d);
        g_start[i] = excl;
        g_cur[i]   = excl;
    }
}

// ---------------- adjacency fill: packed {norm, src} per edge --------------------
__global__ void fill_kernel(const void* __restrict__ eidx) {
    int t = blockIdx.x * blockDim.x + threadIdx.x;
    if (t >= NE) return;
    int s, d;
    if (g_is64) {
        s = (int)((const long long*)eidx)[t];
        d = (int)((const long long*)eidx)[NE + t];
    } else {
        s = ((const int*)eidx)[t];
        d = ((const int*)eidx)[NE + t];
    }
    float norm = g_dinv[s] * g_dinv[d];
    int p = atomicAdd(&g_cur[d], 1);
    g_adj[p] = ((unsigned long long)__float_as_uint(norm) << 32) | (unsigned int)s;
}

// ---------------- GEMM: g_xwh = fp16(x @ W), packed fma.rn.f32x2 -----------------
__global__ void __launch_bounds__(128) gemm_kernel(const float* __restrict__ x,
                                                   const float* __restrict__ W) {
    __shared__ unsigned long long xs[32][DD];   // 32 KB
    const int tid = threadIdx.x;
    const int r0  = blockIdx.x * 32;

    for (int idx = tid; idx < 32 * DD; idx += 128) {
        int row = idx >> 7, k = idx & 127;
        float v = (r0 + row < NN) ? x[(size_t)(r0 + row) * DD + k] : 0.0f;
        unsigned int u = __float_as_uint(v);
        xs[row][k] = ((unsigned long long)u << 32) | u;
    }
    __syncthreads();

    const int cg = tid & 31;    // column group of 4
    const int rg = tid >> 5;    // row group of 8
    unsigned long long a[8][2];
    #pragma unroll
    for (int r = 0; r < 8; r++) { a[r][0] = 0ull; a[r][1] = 0ull; }

    const float4* __restrict__ W4 = (const float4*)W;
    #pragma unroll 4
    for (int k = 0; k < DD; k++) {
        float4 w = W4[k * 32 + cg];             // L1-resident (64 KB)
        unsigned long long wxy, wzw;
        asm("mov.b64 %0, {%1,%2};" : "=l"(wxy) : "f"(w.x), "f"(w.y));
        asm("mov.b64 %0, {%1,%2};" : "=l"(wzw) : "f"(w.z), "f"(w.w));
        #pragma unroll
        for (int r = 0; r < 8; r++) {
            unsigned long long xd = xs[rg * 8 + r][k];
            asm("fma.rn.f32x2 %0, %1, %2, %0;" : "+l"(a[r][0]) : "l"(xd), "l"(wxy));
            asm("fma.rn.f32x2 %0, %1, %2, %0;" : "+l"(a[r][1]) : "l"(xd), "l"(wzw));
        }
    }

    uint2* __restrict__ outh = (uint2*)g_xwh;   // 4 halves per lane per row
    #pragma unroll
    for (int r = 0; r < 8; r++) {
        int row = r0 + rg * 8 + r;
        if (row < NN) {
            float4 o;
            asm("mov.b64 {%0,%1}, %2;" : "=f"(o.x), "=f"(o.y) : "l"(a[r][0]));
            asm("mov.b64 {%0,%1}, %2;" : "=f"(o.z), "=f"(o.w) : "l"(a[r][1]));
            __half2 h01 = __floats2half2_rn(o.x, o.y);
            __half2 h23 = __floats2half2_rn(o.z, o.w);
            uint2 u;
            u.x = *(unsigned int*)&h01;
            u.y = *(unsigned int*)&h23;
            outh[(size_t)row * 32 + cg] = u;
        }
    }
}

// ---- gather: warp per node; self-loop + neighbors + bias + ReLU + BN stats ------
__device__ __forceinline__ float2 h2f(unsigned int h) {
    __half2 hh = *(__half2*)&h;
    return __half22float2(hh);
}

__global__ void __launch_bounds__(256) gather_kernel(const float* __restrict__ bias,
                                                     float* __restrict__ z) {
    const int tid   = threadIdx.x;
    const int lane  = tid & 31;
    const int wid   = tid >> 5;
    const int warpg = (blockIdx.x * 256 + tid) >> 5;
    const int nwarp = gridDim.x * 8;

    const uint2*  __restrict__ xwh   = (const uint2*)g_xwh;
    const float4* __restrict__ bias4 = (const float4*)bias;
    float4*       __restrict__ z4    = (float4*)z;

    const float4 b = bias4[lane];
    float4 ls = make_float4(0.f, 0.f, 0.f, 0.f);
    float4 lq = ls;

    for (int node = warpg; node < NN; node += nwarp) {
        int beg = g_start[node];
        int end = g_cur[node];
        float di = g_dinv[node];
        float sn = di * di;

        uint2 sl = __ldcg(&xwh[(size_t)node * 32 + lane]);
        float2 s01 = h2f(sl.x), s23 = h2f(sl.y);
        float4 acc;
        acc.x = s01.x * sn; acc.y = s01.y * sn;
        acc.z = s23.x * sn; acc.w = s23.y * sn;

        int i = beg;
        for (; i + 4 <= end; i += 4) {
            unsigned long long e0 = g_adj[i];
            unsigned long long e1 = g_adj[i + 1];
            unsigned long long e2 = g_adj[i + 2];
            unsigned long long e3 = g_adj[i + 3];
            uint2 r0 = __ldcg(&xwh[(size_t)(unsigned)(e0 & 0xffffffffu) * 32 + lane]);
            uint2 r1 = __ldcg(&xwh[(size_t)(unsigned)(e1 & 0xffffffffu) * 32 + lane]);
            uint2 r2 = __ldcg(&xwh[(size_t)(unsigned)(e2 & 0xffffffffu) * 32 + lane]);
            uint2 r3 = __ldcg(&xwh[(size_t)(unsigned)(e3 & 0xffffffffu) * 32 + lane]);
            float n0 = __uint_as_float((unsigned)(e0 >> 32));
            float n1 = __uint_as_float((unsigned)(e1 >> 32));
            float n2 = __uint_as_float((unsigned)(e2 >> 32));
            float n3 = __uint_as_float((unsigned)(e3 >> 32));
            float2 a01, a23;
            a01 = h2f(r0.x); a23 = h2f(r0.y);
            acc.x += a01.x * n0; acc.y += a01.y * n0; acc.z += a23.x * n0; acc.w += a23.y * n0;
            a01 = h2f(r1.x); a23 = h2f(r1.y);
            acc.x += a01.x * n1; acc.y += a01.y * n1; acc.z += a23.x * n1; acc.w += a23.y * n1;
            a01 = h2f(r2.x); a23 = h2f(r2.y);
            acc.x += a01.x * n2; acc.y += a01.y * n2; acc.z += a23.x * n2; acc.w += a23.y * n2;
            a01 = h2f(r3.x); a23 = h2f(r3.y);
            acc.x += a01.x * n3; acc.y += a01.y * n3; acc.z += a23.x * n3; acc.w += a23.y * n3;
        }
        for (; i < end; i++) {
            unsigned long long e0 = g_adj[i];
            uint2 r0 = __ldcg(&xwh[(size_t)(unsigned)(e0 & 0xffffffffu) * 32 + lane]);
            float n0 = __uint_as_float((unsigned)(e0 >> 32));
            float2 a01 = h2f(r0.x), a23 = h2f(r0.y);
            acc.x += a01.x * n0; acc.y += a01.y * n0; acc.z += a23.x * n0; acc.w += a23.y * n0;
        }

        float4 v;
        v.x = fmaxf(acc.x + b.x, 0.0f);
        v.y = fmaxf(acc.y + b.y, 0.0f);
        v.z = fmaxf(acc.z + b.z, 0.0f);
        v.w = fmaxf(acc.w + b.w, 0.0f);
        z4[(size_t)node * 32 + lane] = v;

        ls.x += v.x; ls.y += v.y; ls.z += v.z; ls.w += v.w;
        lq.x += v.x * v.x; lq.y += v.y * v.y; lq.z += v.z * v.z; lq.w += v.w * v.w;
    }

    __shared__ float rs[8][DD];
    __shared__ float rq[8][DD];
    ((float4*)&rs[wid][0])[lane] = ls;
    ((float4*)&rq[wid][0])[lane] = lq;
    __syncthreads();
    if (tid < DD) {
        float a = 0.f, q = 0.f;
        #pragma unroll
        for (int w = 0; w < 8; w++) { a += rs[w][tid]; q += rq[w][tid]; }
        atomicAdd(&g_sum[tid], a);
        atomicAdd(&g_sumsq[tid], q);
    }
}

// ---------------- BN affine params ----------------
__global__ void params_kernel(const float* __restrict__ gamma,
                              const float* __restrict__ beta) {
    int j = threadIdx.x;
    float mean = g_sum[j] * (1.0f / NN);
    float var  = g_sumsq[j] * (1.0f / NN) - mean * mean;
    float sc   = gamma[j] * rsqrtf(var + 1e-5f);
    g_scale[j] = sc;
    g_shift[j] = beta[j] - mean * sc;
}

// ---------------- fused normalize + dropout (float4) ----------------
__global__ void __launch_bounds__(256) final_kernel(const float* __restrict__ u,
                                                    float* __restrict__ z) {
    int gid = blockIdx.x * blockDim.x + threadIdx.x;
    if (gid >= NN * 32) return;
    int j4 = (gid & 31) * 4;

    float4 v  = ((const float4*)z)[gid];
    float4 uu = ((const float4*)u)[gid];
    float s0 = g_scale[j4 + 0], s1 = g_scale[j4 + 1], s2 = g_scale[j4 + 2], s3 = g_scale[j4 + 3];
    float h0 = g_shift[j4 + 0], h1 = g_shift[j4 + 1], h2 = g_shift[j4 + 2], h3 = g_shift[j4 + 3];
    const float inv_keep = 1.0f / 0.9f;

    float4 r;
    r.x = (uu.x > 0.1f) ? (v.x * s0 + h0) * inv_keep : 0.0f;
    r.y = (uu.y > 0.1f) ? (v.y * s1 + h1) * inv_keep : 0.0f;
    r.z = (uu.z > 0.1f) ? (v.z * s2 + h2) * inv_keep : 0.0f;
    r.w = (uu.w > 0.1f) ? (v.w * s3 + h3) * inv_keep : 0.0f;
    ((float4*)z)[gid] = r;
}

// ---------------- launch (GEMM forked onto a side stream) ----------------
extern "C" void kernel_launch(void* const* d_in, const int* in_sizes, int n_in,
                              void* d_out, int out_size) {
    const float* x      = (const float*)d_in[0];
    const float* weight = (const float*)d_in[1];
    const float* bias   = (const float*)d_in[2];
    const float* gamma  = (const float*)d_in[3];
    const float* beta   = (const float*)d_in[4];
    const float* drop_u = (const float*)d_in[5];
    const void*  eidx   = d_in[6];

    float* z = (float*)d_out;

    static cudaStream_t s2 = nullptr;
    static cudaEvent_t evf = nullptr, evj = nullptr;
    if (s2 == nullptr) {
        cudaStreamCreateWithFlags(&s2, cudaStreamNonBlocking);
        cudaEventCreateWithFlags(&evf, cudaEventDisableTiming);
        cudaEventCreateWithFlags(&evj, cudaEventDisableTiming);
    }

    // fork: GEMM depends only on inputs
    cudaEventRecord(evf, 0);
    cudaStreamWaitEvent(s2, evf, 0);
    gemm_kernel<<<(NN + 31) / 32, 128, 0, s2>>>(x, weight);
    cudaEventRecord(evj, s2);

    // edge preprocessing chain on the captured (default) stream
    init_kernel<<<(NN + 255) / 256, 256>>>((const unsigned int*)eidx);
    deg_kernel<<<(NE + 255) / 256, 256>>>(eidx);
    scan1_kernel<<<SCAN_G, SCAN_B>>>();
    scan2_kernel<<<1, 64>>>();
    scan3_kernel<<<SCAN_G, SCAN_B>>>();
    fill_kernel<<<(NE + 255) / 256, 256>>>(eidx);

    // join: gather needs both the CSR and the fp16 GEMM output
    cudaStreamWaitEvent(0, evj, 0);
    gather_kernel<<<592, 256>>>(bias, z);
    params_kernel<<<1, DD>>>(gamma, beta);
    final_kernel<<<(NN * 32 + 255) / 256, 256>>>(drop_u, z);
}

// round 5
// speedup vs baseline: 1.8450x; 1.0428x over previous
#include <cuda_runtime.h>
#include <cuda_fp16.h>

#define NN 50000
#define NE 600000
#define DD 128
#define SCAN_B 1024
#define SCAN_G ((NN + SCAN_B - 1) / SCAN_B)   // 49

// ---------------- scratch (static device globals; no allocation) ----------------
__device__ float  g_xw[NN * DD];                // x @ W fp32, 25.6 MB
__device__ __half g_xwh[NN * DD];               // dinv[s] * (x@W)[s] in fp16, 12.8 MB
__device__ int    g_degi[NN];
__device__ int    g_start[NN];
__device__ int    g_cur[NN];
__device__ unsigned int g_adj[NE];              // src only (norm factorized out)
__device__ float  g_dinv[NN];
__device__ int    g_bsum[SCAN_G];
__device__ float  g_sum[DD];
__device__ float  g_sumsq[DD];
__device__ int    g_is64;

// ---------- init (deg=0, stats=0) + dtype detection for edge_index ----------
__global__ void init_kernel(const unsigned int* __restrict__ e) {
    int gid = blockIdx.x * blockDim.x + threadIdx.x;
    if (gid < NN) g_degi[gid] = 0;
    if (gid < DD) { g_sum[gid] = 0.0f; g_sumsq[gid] = 0.0f; }
    if (gid == 0) {
        int is64 = 1;
        #pragma unroll
        for (int i = 0; i < 16; i++) {
            if (e[2 * i + 1] != 0u) { is64 = 0; break; }
        }
        g_is64 = is64;
    }
}

// ---------------- degree over dst ----------------
__global__ void deg_kernel(const void* __restrict__ eidx) {
    int t = blockIdx.x * blockDim.x + threadIdx.x;
    if (t >= NE) return;
    int d;
    if (g_is64) d = (int)((const long long*)eidx)[NE + t];
    else        d = ((const int*)eidx)[NE + t];
    atomicAdd(&g_degi[d], 1);
}

// ---------------- scan phase 1: per-block totals + dinv ----------------
__global__ void __launch_bounds__(SCAN_B) scan1_kernel() {
    __shared__ int wsums[32];
    const int tid = threadIdx.x, lane = tid & 31, wid = tid >> 5;
    const int i = blockIdx.x * SCAN_B + tid;
    int d = (i < NN) ? g_degi[i] : 0;
    if (i < NN) g_dinv[i] = rsqrtf((float)d + 1.0f);   // +1 = self loop

    int v = d;
    #pragma unroll
    for (int o = 16; o > 0; o >>= 1) v += __shfl_down_sync(0xffffffffu, v, o);
    if (lane == 0) wsums[wid] = v;
    __syncthreads();
    if (wid == 0) {
        int wv = wsums[lane];
        #pragma unroll
        for (int o = 16; o > 0; o >>= 1) wv += __shfl_down_sync(0xffffffffu, wv, o);
        if (lane == 0) g_bsum[blockIdx.x] = wv;
    }
}

// -------- scan phase 3 (scan2 inlined): block offset + local scan -> start/cur ---
__global__ void __launch_bounds__(SCAN_B) scan3_kernel() {
    __shared__ int wsums[32];
    __shared__ int bpart[2];
    const int tid = threadIdx.x, lane = tid & 31, wid = tid >> 5;

    // inline exclusive "scan2": sum of g_bsum[0 .. blockIdx.x-1] (<= 48 values)
    if (tid < 64) {
        int t = (tid < (int)blockIdx.x) ? g_bsum[tid] : 0;
        #pragma unroll
        for (int o = 16; o > 0; o >>= 1) t += __shfl_down_sync(0xffffffffu, t, o);
        if (lane == 0) bpart[tid >> 5] = t;
    }

    const int i = blockIdx.x * SCAN_B + tid;
    int d = (i < NN) ? g_degi[i] : 0;
    int v = d;
    #pragma unroll
    for (int o = 1; o < 32; o <<= 1) {
        int t = __shfl_up_sync(0xffffffffu, v, o);
        if (lane >= o) v += t;
    }
    if (lane == 31) wsums[wid] = v;
    __syncthreads();
    if (wid == 0) {
        int wv = wsums[lane];
        #pragma unroll
        for (int o = 1; o < 32; o <<= 1) {
            int t = __shfl_up_sync(0xffffffffu, wv, o);
            if (lane >= o) wv += t;
        }
        wsums[lane] = wv;
    }
    __syncthreads();
    if (i < NN) {
        int boff = bpart[0] + bpart[1];
        int excl = boff + (wid > 0 ? wsums[wid - 1] : 0) + (v - d);
        g_start[i] = excl;
        g_cur[i]   = excl;
    }
}

// ---------------- adjacency fill: src index per edge (no norm needed) ------------
__global__ void fill_kernel(const void* __restrict__ eidx) {
    int t = blockIdx.x * blockDim.x + threadIdx.x;
    if (t >= NE) return;
    int s, d;
    if (g_is64) {
        s = (int)((const long long*)eidx)[t];
        d = (int)((const long long*)eidx)[NE + t];
    } else {
        s = ((const int*)eidx)[t];
        d = ((const int*)eidx)[NE + t];
    }
    int p = atomicAdd(&g_cur[d], 1);
    g_adj[p] = (unsigned int)s;
}

// ---------------- GEMM: g_xw = x @ W (fp32), packed fma.rn.f32x2 -----------------
__global__ void __launch_bounds__(128) gemm_kernel(const float* __restrict__ x,
                                                   const float* __restrict__ W) {
    __shared__ unsigned long long xs[32][DD];   // 32 KB
    const int tid = threadIdx.x;
    const int r0  = blockIdx.x * 32;

    for (int idx = tid; idx < 32 * DD; idx += 128) {
        int row = idx >> 7, k = idx & 127;
        float v = (r0 + row < NN) ? x[(size_t)(r0 + row) * DD + k] : 0.0f;
        unsigned int u = __float_as_uint(v);
        xs[row][k] = ((unsigned long long)u << 32) | u;
    }
    __syncthreads();

    const int cg = tid & 31;
    const int rg = tid >> 5;
    unsigned long long a[8][2];
    #pragma unroll
    for (int r = 0; r < 8; r++) { a[r][0] = 0ull; a[r][1] = 0ull; }

    const float4* __restrict__ W4 = (const float4*)W;
    #pragma unroll 4
    for (int k = 0; k < DD; k++) {
        float4 w = W4[k * 32 + cg];
        unsigned long long wxy, wzw;
        asm("mov.b64 %0, {%1,%2};" : "=l"(wxy) : "f"(w.x), "f"(w.y));
        asm("mov.b64 %0, {%1,%2};" : "=l"(wzw) : "f"(w.z), "f"(w.w));
        #pragma unroll
        for (int r = 0; r < 8; r++) {
            unsigned long long xd = xs[rg * 8 + r][k];
            asm("fma.rn.f32x2 %0, %1, %2, %0;" : "+l"(a[r][0]) : "l"(xd), "l"(wxy));
            asm("fma.rn.f32x2 %0, %1, %2, %0;" : "+l"(a[r][1]) : "l"(xd), "l"(wzw));
        }
    }

    float4* __restrict__ out4 = (float4*)g_xw;
    #pragma unroll
    for (int r = 0; r < 8; r++) {
        int row = r0 + rg * 8 + r;
        if (row < NN) {
            float4 o;
            asm("mov.b64 {%0,%1}, %2;" : "=f"(o.x), "=f"(o.y) : "l"(a[r][0]));
            asm("mov.b64 {%0,%1}, %2;" : "=f"(o.z), "=f"(o.w) : "l"(a[r][1]));
            out4[(size_t)row * 32 + cg] = o;
        }
    }
}

// ------------- prescale: g_xwh[row] = fp16(dinv[row] * g_xw[row]) ----------------
__global__ void __launch_bounds__(256) prescale_kernel() {
    int gid = blockIdx.x * blockDim.x + threadIdx.x;   // NN*32 float4 chunks
    if (gid >= NN * 32) return;
    float di = g_dinv[gid >> 5];
    float4 v = ((const float4*)g_xw)[gid];
    __half2 h01 = __floats2half2_rn(v.x * di, v.y * di);
    __half2 h23 = __floats2half2_rn(v.z * di, v.w * di);
    uint2 u;
    u.x = *(unsigned int*)&h01;
    u.y = *(unsigned int*)&h23;
    ((uint2*)g_xwh)[gid] = u;
}

// ---- gather: warp per node, 2 edges in flight (half-warp per row) ---------------
__device__ __forceinline__ float2 h2f(unsigned int h) {
    __half2 hh = *(__half2*)&h;
    return __half22float2(hh);
}

__global__ void __launch_bounds__(256) gather_kernel(const float* __restrict__ bias,
                                                     float* __restrict__ z) {
    const int tid   = threadIdx.x;
    const int lane  = tid & 31;
    const int wid   = tid >> 5;
    const int g     = lane >> 4;   // half-warp id (0/1)
    const int hl    = lane & 15;   // lane within half-warp -> cols 8*hl..8*hl+7
    const int warpg = (blockIdx.x * 256 + tid) >> 5;
    const int nwarp = gridDim.x * 8;

    const uint4*  __restrict__ xws   = (const uint4*)g_xwh;   // row = 16 uint4
    const float4* __restrict__ bias4 = (const float4*)bias;
    float4*       __restrict__ z4    = (float4*)z;

    const float4 b0 = bias4[2 * hl];
    const float4 b1 = bias4[2 * hl + 1];
    float ls[8], lq[8];
    #pragma unroll
    for (int k = 0; k < 8; k++) { ls[k] = 0.f; lq[k] = 0.f; }

    for (int node = warpg; node < NN; node += nwarp) {
        const int beg = g_start[node];
        const int end = g_cur[node];
        const float di = g_dinv[node];

        float a[8];
        #pragma unroll
        for (int k = 0; k < 8; k++) a[k] = 0.f;

        // self loop: xws[node] added once (only half-warp 0)
        if (g == 0) {
            uint4 r = __ldcg(&xws[(size_t)node * 16 + hl]);
            float2 p0 = h2f(r.x), p1 = h2f(r.y), p2 = h2f(r.z), p3 = h2f(r.w);
            a[0] += p0.x; a[1] += p0.y; a[2] += p1.x; a[3] += p1.y;
            a[4] += p2.x; a[5] += p2.y; a[6] += p3.x; a[7] += p3.y;
        }

        for (int base = beg; base < end; base += 32) {
            const int cnt = min(32, end - base);
            unsigned int sv = (lane < cnt) ? g_adj[base + lane] : 0u;  // coalesced batch
            #pragma unroll 4
            for (int j = 0; j < cnt; j += 2) {
                int e = j + g;
                unsigned int sj = __shfl_sync(0xffffffffu, sv, e & 31);
                if (e < cnt) {
                    uint4 r = __ldcg(&xws[(size_t)sj * 16 + hl]);
                    float2 p0 = h2f(r.x), p1 = h2f(r.y), p2 = h2f(r.z), p3 = h2f(r.w);
                    a[0] += p0.x; a[1] += p0.y; a[2] += p1.x; a[3] += p1.y;
                    a[4] += p2.x; a[5] += p2.y; a[6] += p3.x; a[7] += p3.y;
                }
            }
        }

        // combine the two half-warps
        #pragma unroll
        for (int k = 0; k < 8; k++) a[k] += __shfl_xor_sync(0xffffffffu, a[k], 16);

        if (g == 0) {
            float4 v0, v1;
            v0.x = fmaxf(a[0] * di + b0.x, 0.0f);
            v0.y = fmaxf(a[1] * di + b0.y, 0.0f);
            v0.z = fmaxf(a[2] * di + b0.z, 0.0f);
            v0.w = fmaxf(a[3] * di + b0.w, 0.0f);
            v1.x = fmaxf(a[4] * di + b1.x, 0.0f);
            v1.y = fmaxf(a[5] * di + b1.y, 0.0f);
            v1.z = fmaxf(a[6] * di + b1.z, 0.0f);
            v1.w = fmaxf(a[7] * di + b1.w, 0.0f);
            z4[(size_t)node * 32 + 2 * hl]     = v0;
            z4[(size_t)node * 32 + 2 * hl + 1] = v1;
            ls[0] += v0.x; ls[1] += v0.y; ls[2] += v0.z; ls[3] += v0.w;
            ls[4] += v1.x; ls[5] += v1.y; ls[6] += v1.z; ls[7] += v1.w;
            lq[0] += v0.x * v0.x; lq[1] += v0.y * v0.y; lq[2] += v0.z * v0.z; lq[3] += v0.w * v0.w;
            lq[4] += v1.x * v1.x; lq[5] += v1.y * v1.y; lq[6] += v1.z * v1.z; lq[7] += v1.w * v1.w;
        }
    }

    __shared__ float rs[8][DD];
    __shared__ float rq[8][DD];
    if (g == 0) {
        float4* prs = (float4*)&rs[wid][hl * 8];
        float4* prq = (float4*)&rq[wid][hl * 8];
        prs[0] = make_float4(ls[0], ls[1], ls[2], ls[3]);
        prs[1] = make_float4(ls[4], ls[5], ls[6], ls[7]);
        prq[0] = make_float4(lq[0], lq[1], lq[2], lq[3]);
        prq[1] = make_float4(lq[4], lq[5], lq[6], lq[7]);
    }
    __syncthreads();
    if (tid < DD) {
        float s = 0.f, q = 0.f;
        #pragma unroll
        for (int w = 0; w < 8; w++) { s += rs[w][tid]; q += rq[w][tid]; }
        atomicAdd(&g_sum[tid], s);
        atomicAdd(&g_sumsq[tid], q);
    }
}

// --------- fused BN params + normalize + dropout (params recomputed/block) -------
__global__ void __launch_bounds__(256) final_kernel(const float* __restrict__ gamma,
                                                    const float* __restrict__ beta,
                                                    const float* __restrict__ u,
                                                    float* __restrict__ z) {
    __shared__ float sc[DD], sh[DD];
    const int tid = threadIdx.x;
    if (tid < DD) {
        float mean = g_sum[tid] * (1.0f / NN);
        float var  = g_sumsq[tid] * (1.0f / NN) - mean * mean;
        float s    = gamma[tid] * rsqrtf(var + 1e-5f);
        sc[tid] = s;
        sh[tid] = beta[tid] - mean * s;
    }
    __syncthreads();

    int gid = blockIdx.x * blockDim.x + tid;
    if (gid >= NN * 32) return;
    int j4 = (gid & 31) * 4;

    float4 v  = ((const float4*)z)[gid];
    float4 uu = ((const float4*)u)[gid];
    const float inv_keep = 1.0f / 0.9f;

    float4 r;
    r.x = (uu.x > 0.1f) ? (v.x * sc[j4 + 0] + sh[j4 + 0]) * inv_keep : 0.0f;
    r.y = (uu.y > 0.1f) ? (v.y * sc[j4 + 1] + sh[j4 + 1]) * inv_keep : 0.0f;
    r.z = (uu.z > 0.1f) ? (v.z * sc[j4 + 2] + sh[j4 + 2]) * inv_keep : 0.0f;
    r.w = (uu.w > 0.1f) ? (v.w * sc[j4 + 3] + sh[j4 + 3]) * inv_keep : 0.0f;
    ((float4*)z)[gid] = r;
}

// ---------------- launch (GEMM+prescale forked onto a side stream) ---------------
extern "C" void kernel_launch(void* const* d_in, const int* in_sizes, int n_in,
                              void* d_out, int out_size) {
    const float* x      = (const float*)d_in[0];
    const float* weight = (const float*)d_in[1];
    const float* bias   = (const float*)d_in[2];
    const float* gamma  = (const float*)d_in[3];
    const float* beta   = (const float*)d_in[4];
    const float* drop_u = (const float*)d_in[5];
    const void*  eidx   = d_in[6];

    float* z = (float*)d_out;

    static cudaStream_t s2 = nullptr;
    static cudaEvent_t evf = nullptr, evd = nullptr, evj = nullptr;
    if (s2 == nullptr) {
        cudaStreamCreateWithFlags(&s2, cudaStreamNonBlocking);
        cudaEventCreateWithFlags(&evf, cudaEventDisableTiming);
        cudaEventCreateWithFlags(&evd, cudaEventDisableTiming);
        cudaEventCreateWithFlags(&evj, cudaEventDisableTiming);
    }

    // fork GEMM (depends only on inputs)
    cudaEventRecord(evf, 0);
    cudaStreamWaitEvent(s2, evf, 0);
    gemm_kernel<<<(NN + 31) / 32, 128, 0, s2>>>(x, weight);

    // main chain: edge preprocessing
    init_kernel<<<(NN + 255) / 256, 256>>>((const unsigned int*)eidx);
    deg_kernel<<<(NE + 255) / 256, 256>>>(eidx);
    scan1_kernel<<<SCAN_G, SCAN_B>>>();
    cudaEventRecord(evd, 0);                     // dinv ready
    scan3_kernel<<<SCAN_G, SCAN_B>>>();
    fill_kernel<<<(NE + 255) / 256, 256>>>(eidx);

    // side stream: prescale needs GEMM + dinv
    cudaStreamWaitEvent(s2, evd, 0);
    prescale_kernel<<<(NN * 32 + 255) / 256, 256, 0, s2>>>();
    cudaEventRecord(evj, s2);

    // join: gather needs CSR + prescaled rows
    cudaStreamWaitEvent(0, evj, 0);
    gather_kernel<<<592, 256>>>(bias, z);
    final_kernel<<<(NN * 32 + 255) / 256, 256>>>(gamma, beta, drop_u, z);
}